// round 15
// baseline (speedup 1.0000x reference)
#include <cuda_runtime.h>
#include <cuda_bf16.h>
#include <cstdint>

// R15: R14 + (a) Stage A consumes fp32 features directly (cp.async fp32 ->
// smem staging -> in-smem bf16 convert), deleting the 13us feat-prep pass;
// (b) final loss division folded into the edge kernel (last-block pattern).

namespace {
constexpr int NHID     = 128;
constexpr int PRE_N    = 256;                 // u(128) | v(128)
constexpr int PRE_K    = 128;
constexpr int TILE_M   = 128;
constexpr int PRE_THREADS = 512;
constexpr int N_NODES_PAD = 100096;           // 782 * 128
constexpr int PRE_B_BYTES = PRE_K * PRE_N * 2;    // 64 KB W1 image
constexpr int F_BYTES    = TILE_M * PRE_K * 4;    // 64 KB fp32 staging tile
constexpr int A_BYTES    = TILE_M * PRE_K * 2;    // 32 KB bf16 A tile
constexpr int OFF_F0 = PRE_B_BYTES;
constexpr int OFF_F1 = PRE_B_BYTES + F_BYTES;
constexpr int OFF_A  = PRE_B_BYTES + 2 * F_BYTES;
constexpr int PRE_DSMEM = OFF_A + A_BYTES + 1024;
constexpr int EDGE_THREADS = 256;
constexpr int W1_ELEMS = PRE_K * PRE_N;           // 32768
}

__device__ __align__(16) __nv_bfloat16 g_w1pre[W1_ELEMS];   // swizzled B image
__device__ __align__(16) __nv_bfloat16 g_uv[(size_t)N_NODES_PAD * PRE_N];
__device__ double g_loss_sum;
__device__ unsigned int g_cnt;

__device__ __forceinline__ uint32_t smem_u32(const void* p) {
    uint32_t a;
    asm("{ .reg .u64 t; cvta.to.shared.u64 t, %1; cvt.u32.u64 %0, t; }" : "=r"(a) : "l"(p));
    return a;
}

#define LDSM_X4(r, addr) \
    asm volatile("ldmatrix.sync.aligned.m8n8.x4.shared.b16 {%0,%1,%2,%3}, [%4];" \
        : "=r"((r)[0]), "=r"((r)[1]), "=r"((r)[2]), "=r"((r)[3]) : "r"(addr))
#define LDSM_X4T(r, addr) \
    asm volatile("ldmatrix.sync.aligned.m8n8.x4.trans.shared.b16 {%0,%1,%2,%3}, [%4];" \
        : "=r"((r)[0]), "=r"((r)[1]), "=r"((r)[2]), "=r"((r)[3]) : "r"(addr))

// ---------------- prep: loss init + W1 image (feat conversion now fused) ----------------
__global__ void hx_prep(const float* __restrict__ W1)
{
    const int idx = blockIdx.x * blockDim.x + threadIdx.x;
    if (idx == 0) { g_loss_sum = 0.0; g_cnt = 0u; }
    if (idx < W1_ELEMS) {
        const int k = idx >> 8, np = idx & 255;
        const int srow = k + ((np >> 7) << 7);
        const int scol = np & 127;
        const int c  = np >> 3;
        const int cs = (c & 24) | ((c & 7) ^ (k & 7));
        const uint32_t off = (uint32_t)k * 512u + (uint32_t)cs * 16u + (uint32_t)(np & 7) * 2u;
        *reinterpret_cast<__nv_bfloat16*>(reinterpret_cast<char*>(g_w1pre) + off) =
            __float2bfloat16(W1[srow * 128 + scol]);
    }
}

// ---------------- Stage A: node GEMM uv = feat @ [W1_top | W1_bot] ----------------
// cp.async 64KB fp32 tile (row r = 512B; thread: r=tid>>2, part=tid&3, 8x16B)
__device__ __forceinline__ void pre_gather_f32(uint32_t Fbuf, int t, int tid,
                                               const float* __restrict__ feat,
                                               int nmax) {
    const int r = tid >> 2, part = tid & 3;
    int node = t * TILE_M + r;
    if (node > nmax) node = nmax;
    const char* src = reinterpret_cast<const char*>(feat + (size_t)node * PRE_K)
                    + part * 128;
    const uint32_t dst = Fbuf + (uint32_t)r * 512u + (uint32_t)part * 128u;
    #pragma unroll
    for (int q = 0; q < 8; ++q)
        asm volatile("cp.async.cg.shared.global [%0], [%1], 16;"
                     :: "r"(dst + (uint32_t)q * 16u), "l"(src + q * 16) : "memory");
}

__global__ __launch_bounds__(PRE_THREADS, 1)
void hx_pre_gemm(const float* __restrict__ feature,
                 const float* __restrict__ b1, int ntiles, int nmax)
{
    extern __shared__ char dyn[];
    const int tid  = threadIdx.x;
    const int lane = tid & 31;
    const int warp = tid >> 5;

    const uint32_t dynb = smem_u32(dyn);
    const uint32_t base = (dynb + 1023u) & ~1023u;
    char* dynbase = dyn + (base - dynb);
    const uint32_t Bsm  = base;
    const uint32_t Abuf = base + OFF_A;

    const int warp_m = warp & 1, warp_n = warp >> 1;
    const int m_base = warp_m * 64, n_base = warp_n * 32;
    const int quad = lane >> 2, qlane = lane & 3;

    if (blockIdx.x < ntiles)
        pre_gather_f32(base + OFF_F0, blockIdx.x, tid, feature, nmax);
    asm volatile("cp.async.commit_group;" ::: "memory");
    {   // stage W1 image
        const int4* s = reinterpret_cast<const int4*>(g_w1pre);
        int4* d = reinterpret_cast<int4*>(dynbase);
        for (int i = tid; i < PRE_B_BYTES / 16; i += PRE_THREADS) d[i] = s[i];
    }

    float2 bb[4];
    #pragma unroll
    for (int j = 0; j < 4; ++j) {
        const int n = n_base + j * 8 + qlane * 2;
        bb[j] = (n < 128) ? make_float2(b1[n], b1[n + 1]) : make_float2(0.f, 0.f);
    }

    uint32_t rowA[4];
    #pragma unroll
    for (int i = 0; i < 4; ++i)
        rowA[i] = Abuf + (uint32_t)(m_base + i * 16 + (lane & 15)) * 256u;
    const int xA  = lane & 7;
    const int csA = lane >> 4;

    uint32_t bBase[2];
    {
        const int kr = lane & 15;
        #pragma unroll
        for (int j2 = 0; j2 < 2; ++j2) {
            const int cn = warp_n * 4 + j2 * 2 + (lane >> 4);
            const int cs = (cn & 24) | ((cn & 7) ^ (kr & 7));
            bBase[j2] = Bsm + (uint32_t)kr * 512u + (uint32_t)cs * 16u;
        }
    }

    // convert-pass constants (thread -> 8 float4 reads, 8 swizzled 8B writes)
    const int cv_row0 = tid >> 5;                 // + 16k
    const int cv_lc   = tid & 31;
    const int cv_c    = cv_lc >> 1;
    const uint32_t cv_woff = 8u * (uint32_t)(cv_lc & 1);

    int li = 0;
    for (int t = blockIdx.x; t < ntiles; t += gridDim.x, ++li) {
        const int buf = li & 1;
        char* Fsm = dynbase + (buf ? OFF_F1 : OFF_F0);

        asm volatile("cp.async.wait_group 0;" ::: "memory");
        __syncthreads();    // F[buf] ready; previous GEMM done (A reusable)

        const int tn = t + gridDim.x;
        if (tn < ntiles) {
            pre_gather_f32(base + (buf ? OFF_F0 : OFF_F1), tn, tid, feature, nmax);
            asm volatile("cp.async.commit_group;" ::: "memory");
        }

        // ---- convert F[buf] fp32 -> A bf16 (swizzled) ----
        #pragma unroll
        for (int k = 0; k < 8; ++k) {
            const float4 v = *reinterpret_cast<const float4*>(
                Fsm + ((size_t)tid + 512 * k) * 16);
            const int r = cv_row0 + 16 * k;
            const int cs = (cv_c & 8) | ((cv_c & 7) ^ (r & 7));
            const uint32_t addr = Abuf + (uint32_t)r * 256u
                                + (uint32_t)cs * 16u + cv_woff;
            const __nv_bfloat162 p0 = __floats2bfloat162_rn(v.x, v.y);
            const __nv_bfloat162 p1 = __floats2bfloat162_rn(v.z, v.w);
            uint64_t packed;
            asm("mov.b64 %0, {%1, %2};" : "=l"(packed)
                : "r"(*reinterpret_cast<const uint32_t*>(&p0)),
                  "r"(*reinterpret_cast<const uint32_t*>(&p1)));
            asm volatile("st.shared.b64 [%0], %1;" :: "r"(addr), "l"(packed) : "memory");
        }
        __syncthreads();    // A complete before GEMM reads

        float acc[4][4][4];
        #pragma unroll
        for (int i = 0; i < 4; ++i)
            #pragma unroll
            for (int j = 0; j < 4; ++j) {
                acc[i][j][0] = 0.f; acc[i][j][1] = 0.f;
                acc[i][j][2] = 0.f; acc[i][j][3] = 0.f;
            }

        #pragma unroll
        for (int ks = 0; ks < 8; ++ks) {
            uint32_t b[2][4], a[4][4];
            #pragma unroll
            for (int j2 = 0; j2 < 2; ++j2)
                LDSM_X4T(b[j2], bBase[j2] + (uint32_t)ks * 8192u);
            const int c  = 2 * ks + csA;
            const int cs = (c & 8) | ((c & 7) ^ xA);
            #pragma unroll
            for (int i = 0; i < 4; ++i)
                LDSM_X4(a[i], rowA[i] + (uint32_t)cs * 16u);
            #pragma unroll
            for (int i = 0; i < 4; ++i)
                #pragma unroll
                for (int j = 0; j < 4; ++j) {
                    const uint32_t bb0 = b[j >> 1][(j & 1) * 2];
                    const uint32_t bb1 = b[j >> 1][(j & 1) * 2 + 1];
                    asm volatile(
                        "mma.sync.aligned.m16n8k16.row.col.f32.bf16.bf16.f32 "
                        "{%0,%1,%2,%3}, {%4,%5,%6,%7}, {%8,%9}, {%0,%1,%2,%3};"
                        : "+f"(acc[i][j][0]), "+f"(acc[i][j][1]),
                          "+f"(acc[i][j][2]), "+f"(acc[i][j][3])
                        : "r"(a[i][0]), "r"(a[i][1]), "r"(a[i][2]), "r"(a[i][3]),
                          "r"(bb0), "r"(bb1));
                }
        }

        #pragma unroll
        for (int i = 0; i < 4; ++i) {
            const int m0 = m_base + i * 16 + quad;
            const size_t r0 = (size_t)(t * TILE_M + m0) * PRE_N;
            const size_t r1 = (size_t)(t * TILE_M + m0 + 8) * PRE_N;
            #pragma unroll
            for (int j = 0; j < 4; ++j) {
                const int n = n_base + j * 8 + qlane * 2;
                __nv_bfloat162 p = __floats2bfloat162_rn(acc[i][j][0] + bb[j].x,
                                                         acc[i][j][1] + bb[j].y);
                __nv_bfloat162 q = __floats2bfloat162_rn(acc[i][j][2] + bb[j].x,
                                                         acc[i][j][3] + bb[j].y);
                *reinterpret_cast<__nv_bfloat162*>(&g_uv[r0 + n]) = p;
                *reinterpret_cast<__nv_bfloat162*>(&g_uv[r1 + n]) = q;
            }
        }
    }
}

// ---------------- Stage B: per-edge loss + fused finalization ----------------
__global__ __launch_bounds__(EDGE_THREADS, 2)
void hx_edge(const float* __restrict__ alpha,
             const float* __restrict__ W2,
             const float* __restrict__ b2,
             const int* __restrict__ row,
             const int* __restrict__ col,
             const int* __restrict__ label,
             int E, float* __restrict__ out)
{
    __shared__ double s_dsum;
    const int tid  = threadIdx.x;
    const int lane = tid & 31;
    const int warp = tid >> 5;
    if (tid == 0) s_dsum = 0.0;
    __syncthreads();

    const int sub = lane >> 3;         // edge within group (0..3)
    const int sl  = lane & 7;          // lane within edge (0..7)
    const int ch0 = sl * 16;           // 16 channels per lane

    __nv_bfloat162 al2[8];
    float wa[16], wb[16];
    #pragma unroll
    for (int i = 0; i < 8; ++i)
        al2[i] = __floats2bfloat162_rn(__ldg(&alpha[ch0 + 2 * i]),
                                       __ldg(&alpha[ch0 + 2 * i + 1]));
    #pragma unroll
    for (int i = 0; i < 16; ++i) {
        wa[i] = __ldg(&W2[(ch0 + i) * 2]);
        wb[i] = __ldg(&W2[(ch0 + i) * 2 + 1]);
    }
    const float bias0 = b2[0], bias1 = b2[1];
    const __nv_bfloat162 z2 = __floats2bfloat162_rn(0.f, 0.f);

    const int gw = blockIdx.x * (EDGE_THREADS / 32) + warp;
    const int nw = gridDim.x * (EDGE_THREADS / 32);
    const int NG = (E + 3) >> 2;       // groups of 4 edges

    double dsum = 0.0;

    if (gw < NG) {
        int e0 = gw * 4 + sub; if (e0 >= E) e0 = E - 1;
        int la = 0, lb = 0;
        uint4 Ua, Ub, Va, Vb;
        {
            const int rc = __ldg(&row[e0]), cc = __ldg(&col[e0]);
            la = __ldg(&label[rc]); lb = __ldg(&label[cc]);
            const __nv_bfloat16* uP = &g_uv[(size_t)rc * PRE_N + ch0];
            const __nv_bfloat16* vP = &g_uv[(size_t)cc * PRE_N + 128 + ch0];
            Ua = *reinterpret_cast<const uint4*>(uP);
            Ub = *reinterpret_cast<const uint4*>(uP + 8);
            Va = *reinterpret_cast<const uint4*>(vP);
            Vb = *reinterpret_cast<const uint4*>(vP + 8);
        }
        int rn = 0, cn = 0;
        if (gw + nw < NG) {
            int e1 = (gw + nw) * 4 + sub; if (e1 >= E) e1 = E - 1;
            rn = __ldg(&row[e1]); cn = __ldg(&col[e1]);
        }

        for (int g = gw; g < NG; g += nw) {
            const int g1 = g + nw;

            uint4 nUa, nUb, nVa, nVb;
            int lan = 0, lbn = 0;
            if (g1 < NG) {
                const __nv_bfloat16* uP = &g_uv[(size_t)rn * PRE_N + ch0];
                const __nv_bfloat16* vP = &g_uv[(size_t)cn * PRE_N + 128 + ch0];
                nUa = *reinterpret_cast<const uint4*>(uP);
                nUb = *reinterpret_cast<const uint4*>(uP + 8);
                nVa = *reinterpret_cast<const uint4*>(vP);
                nVb = *reinterpret_cast<const uint4*>(vP + 8);
                lan = __ldg(&label[rn]);
                lbn = __ldg(&label[cn]);
            } else {
                nUa = make_uint4(0,0,0,0); nUb = nUa; nVa = nUa; nVb = nUa;
            }
            int rn2 = 0, cn2 = 0;
            if (g + 2 * nw < NG) {
                int e2 = (g + 2 * nw) * 4 + sub; if (e2 >= E) e2 = E - 1;
                rn2 = __ldg(&row[e2]); cn2 = __ldg(&col[e2]);
            }

            float p0 = 0.f, p1 = 0.f;
            const uint32_t uw[8] = {Ua.x, Ua.y, Ua.z, Ua.w, Ub.x, Ub.y, Ub.z, Ub.w};
            const uint32_t vw[8] = {Va.x, Va.y, Va.z, Va.w, Vb.x, Vb.y, Vb.z, Vb.w};
            #pragma unroll
            for (int i = 0; i < 8; ++i) {
                const __nv_bfloat162 u2 = *reinterpret_cast<const __nv_bfloat162*>(&uw[i]);
                const __nv_bfloat162 v2 = *reinterpret_cast<const __nv_bfloat162*>(&vw[i]);
                const __nv_bfloat162 h2 = __hadd2(u2, v2);
                const __nv_bfloat162 ph2 =
                    __hfma2(al2[i], __hmin2(h2, z2), __hmax2(h2, z2));
                const float2 f = __bfloat1622float2(ph2);
                p0 = fmaf(f.x, wa[2 * i], p0);      p1 = fmaf(f.x, wb[2 * i], p1);
                p0 = fmaf(f.y, wa[2 * i + 1], p0);  p1 = fmaf(f.y, wb[2 * i + 1], p1);
            }
            #pragma unroll
            for (int off = 4; off > 0; off >>= 1) {
                p0 += __shfl_xor_sync(0xffffffffu, p0, off);
                p1 += __shfl_xor_sync(0xffffffffu, p1, off);
            }
            if (sl == 0) {
                const int ecur = g * 4 + sub;
                if (ecur < E) {
                    const float l0 = p0 + bias0;
                    const float l1 = p1 + bias1;
                    const float mx  = fmaxf(l0, l1);
                    const float lse = mx + log1pf(expf(-fabsf(l0 - l1)));
                    dsum += (double)(((la == lb) ? l1 : l0) - lse);
                }
            }

            Ua = nUa; Ub = nUb; Va = nVa; Vb = nVb;
            la = lan; lb = lbn;
            rn = rn2; cn = cn2;
        }
    }

    if (sl == 0) atomicAdd(&s_dsum, dsum);
    __syncthreads();
    if (tid == 0) {
        atomicAdd(&g_loss_sum, s_dsum);
        __threadfence();
        const unsigned int n = atomicAdd(&g_cnt, 1u);
        if (n == gridDim.x - 1) {
            const double total = atomicAdd(&g_loss_sum, 0.0);   // ordered read
            out[0] = (float)(-total / (double)E);
        }
    }
}

extern "C" void kernel_launch(void* const* d_in, const int* in_sizes, int n_in,
                              void* d_out, int out_size) {
    const float* feature = (const float*)d_in[0];
    const float* W1      = (const float*)d_in[1];
    const float* b1      = (const float*)d_in[2];
    const float* alpha   = (const float*)d_in[3];
    const float* W2      = (const float*)d_in[4];
    const float* b2      = (const float*)d_in[5];
    const int*   row     = (const int*)d_in[6];
    const int*   col     = (const int*)d_in[7];
    const int*   label   = (const int*)d_in[8];
    const int E  = in_sizes[6];
    const int nf = in_sizes[0];
    float* out = (float*)d_out;

    int sms = 148;
    cudaDeviceGetAttribute(&sms, cudaDevAttrMultiProcessorCount, 0);
    cudaFuncSetAttribute(hx_pre_gemm,
                         cudaFuncAttributeMaxDynamicSharedMemorySize, PRE_DSMEM);

    hx_prep<<<(W1_ELEMS + 255) / 256, 256>>>(W1);

    const int nnodes = nf / NHID;
    const int ntiles = (nnodes + TILE_M - 1) / TILE_M;
    hx_pre_gemm<<<sms, PRE_THREADS, PRE_DSMEM>>>(feature, b1, ntiles, nnodes - 1);

    hx_edge<<<sms * 2, EDGE_THREADS>>>(alpha, W2, b2, row, col, label, E, out);
}

// round 16
// speedup vs baseline: 1.0336x; 1.0336x over previous
#include <cuda_runtime.h>
#include <cuda_bf16.h>
#include <cstdint>

// R16: consolidation. Stage A = R14's verified bf16-table GEMM (36us);
// feat fp32->bf16 conversion back in the merged prep kernel (bandwidth-
// optimal 13us); finalize fused into hx_edge (R15's last-block pattern).
// 3 launches total.

namespace {
constexpr int NHID     = 128;
constexpr int PRE_N    = 256;                 // u(128) | v(128)
constexpr int PRE_K    = 128;
constexpr int TILE_M   = 128;
constexpr int PRE_THREADS = 512;
constexpr int N_NODES_PAD = 100096;           // 782 * 128
constexpr int PRE_B_BYTES = PRE_K * PRE_N * 2;    // 64 KB
constexpr int PRE_A_BYTES = TILE_M * PRE_K * 2;   // 32 KB
constexpr int PRE_DSMEM   = PRE_B_BYTES + 2 * PRE_A_BYTES + 256;
constexpr int EDGE_THREADS = 256;
constexpr int W1_ELEMS = PRE_K * PRE_N;           // 32768
}

__device__ __align__(16) __nv_bfloat16 g_feat_bf16[(size_t)100000 * NHID];
__device__ __align__(16) __nv_bfloat16 g_w1pre[W1_ELEMS];   // swizzled B image
__device__ __align__(16) __nv_bfloat16 g_uv[(size_t)N_NODES_PAD * PRE_N];
__device__ double g_loss_sum;
__device__ unsigned int g_cnt;

__device__ __forceinline__ uint32_t smem_u32(const void* p) {
    uint32_t a;
    asm("{ .reg .u64 t; cvta.to.shared.u64 t, %1; cvt.u32.u64 %0, t; }" : "=r"(a) : "l"(p));
    return a;
}

#define LDSM_X4(r, addr) \
    asm volatile("ldmatrix.sync.aligned.m8n8.x4.shared.b16 {%0,%1,%2,%3}, [%4];" \
        : "=r"((r)[0]), "=r"((r)[1]), "=r"((r)[2]), "=r"((r)[3]) : "r"(addr))
#define LDSM_X4T(r, addr) \
    asm volatile("ldmatrix.sync.aligned.m8n8.x4.trans.shared.b16 {%0,%1,%2,%3}, [%4];" \
        : "=r"((r)[0]), "=r"((r)[1]), "=r"((r)[2]), "=r"((r)[3]) : "r"(addr))

// ---------------- merged prep: loss init + feat fp32->bf16 + W1 image ----------------
__global__ void hx_prep(const float* __restrict__ f,
                        const float* __restrict__ W1, int n4)
{
    const int i = blockIdx.x * blockDim.x + threadIdx.x;
    if (i == 0) { g_loss_sum = 0.0; g_cnt = 0u; }
    if (i < n4) {
        float4 v = reinterpret_cast<const float4*>(f)[i];
        __nv_bfloat162* dst = reinterpret_cast<__nv_bfloat162*>(g_feat_bf16);
        dst[i * 2]     = __floats2bfloat162_rn(v.x, v.y);
        dst[i * 2 + 1] = __floats2bfloat162_rn(v.z, v.w);
    } else if (i < n4 + W1_ELEMS) {
        const int idx = i - n4;
        const int k = idx >> 8, np = idx & 255;
        const int srow = k + ((np >> 7) << 7);
        const int scol = np & 127;
        const int c  = np >> 3;
        const int cs = (c & 24) | ((c & 7) ^ (k & 7));
        const uint32_t off = (uint32_t)k * 512u + (uint32_t)cs * 16u + (uint32_t)(np & 7) * 2u;
        *reinterpret_cast<__nv_bfloat16*>(reinterpret_cast<char*>(g_w1pre) + off) =
            __float2bfloat16(W1[srow * 128 + scol]);
    }
}

// ---------------- Stage A: node GEMM uv = feat @ [W1_top | W1_bot] ----------------
__device__ __forceinline__ void pre_gather(uint32_t Abuf, int t, int tid) {
    const int r = tid >> 2, part = tid & 3;
    int node = t * TILE_M + r;
    if (node > 99999) node = 99999;
    const char* src = reinterpret_cast<const char*>(g_feat_bf16) + (size_t)node * 256;
    #pragma unroll
    for (int q = 0; q < 4; ++q) {
        const int c  = part * 4 + q;
        const int cs = (c & 8) | ((c & 7) ^ (r & 7));
        asm volatile("cp.async.cg.shared.global [%0], [%1], 16;"
                     :: "r"(Abuf + (uint32_t)r * 256u + (uint32_t)cs * 16u),
                        "l"(src + c * 16) : "memory");
    }
}

__global__ __launch_bounds__(PRE_THREADS, 1)
void hx_pre_gemm(const float* __restrict__ b1, int ntiles)
{
    extern __shared__ char dyn[];
    const int tid  = threadIdx.x;
    const int lane = tid & 31;
    const int warp = tid >> 5;

    const uint32_t dynb = smem_u32(dyn);
    const uint32_t base = (dynb + 255u) & ~255u;
    const uint32_t Bsm  = base;
    const uint32_t Asm0 = base + PRE_B_BYTES;

    const int warp_m = warp & 1, warp_n = warp >> 1;
    const int m_base = warp_m * 64, n_base = warp_n * 32;
    const int quad = lane >> 2, qlane = lane & 3;

    if (blockIdx.x < ntiles) pre_gather(Asm0, blockIdx.x, tid);
    asm volatile("cp.async.commit_group;" ::: "memory");
    {
        char* dst = dyn + (base - dynb);
        const int4* s = reinterpret_cast<const int4*>(g_w1pre);
        int4* d = reinterpret_cast<int4*>(dst);
        for (int i = tid; i < PRE_B_BYTES / 16; i += PRE_THREADS) d[i] = s[i];
    }

    float2 bb[4];
    #pragma unroll
    for (int j = 0; j < 4; ++j) {
        const int n = n_base + j * 8 + qlane * 2;
        bb[j] = (n < 128) ? make_float2(b1[n], b1[n + 1]) : make_float2(0.f, 0.f);
    }

    uint32_t rowA[4];
    #pragma unroll
    for (int i = 0; i < 4; ++i)
        rowA[i] = (uint32_t)(m_base + i * 16 + (lane & 15)) * 256u;
    const int xA  = lane & 7;
    const int csA = lane >> 4;

    uint32_t bBase[2];
    {
        const int kr = lane & 15;
        #pragma unroll
        for (int j2 = 0; j2 < 2; ++j2) {
            const int cn = warp_n * 4 + j2 * 2 + (lane >> 4);
            const int cs = (cn & 24) | ((cn & 7) ^ (kr & 7));
            bBase[j2] = Bsm + (uint32_t)kr * 512u + (uint32_t)cs * 16u;
        }
    }

    int li = 0;
    for (int t = blockIdx.x; t < ntiles; t += gridDim.x, ++li) {
        const int buf = li & 1;
        const uint32_t Abuf = Asm0 + (uint32_t)buf * PRE_A_BYTES;

        asm volatile("cp.async.wait_group 0;" ::: "memory");
        __syncthreads();

        const int tn = t + gridDim.x;
        if (tn < ntiles) {
            pre_gather(Asm0 + (uint32_t)(buf ^ 1) * PRE_A_BYTES, tn, tid);
            asm volatile("cp.async.commit_group;" ::: "memory");
        }

        float acc[4][4][4];
        #pragma unroll
        for (int i = 0; i < 4; ++i)
            #pragma unroll
            for (int j = 0; j < 4; ++j) {
                acc[i][j][0] = 0.f; acc[i][j][1] = 0.f;
                acc[i][j][2] = 0.f; acc[i][j][3] = 0.f;
            }

        #pragma unroll
        for (int ks = 0; ks < 8; ++ks) {
            uint32_t b[2][4], a[4][4];
            #pragma unroll
            for (int j2 = 0; j2 < 2; ++j2)
                LDSM_X4T(b[j2], bBase[j2] + (uint32_t)ks * 8192u);
            const int c  = 2 * ks + csA;
            const int cs = (c & 8) | ((c & 7) ^ xA);
            #pragma unroll
            for (int i = 0; i < 4; ++i)
                LDSM_X4(a[i], Abuf + rowA[i] + (uint32_t)cs * 16u);
            #pragma unroll
            for (int i = 0; i < 4; ++i)
                #pragma unroll
                for (int j = 0; j < 4; ++j) {
                    const uint32_t bb0 = b[j >> 1][(j & 1) * 2];
                    const uint32_t bb1 = b[j >> 1][(j & 1) * 2 + 1];
                    asm volatile(
                        "mma.sync.aligned.m16n8k16.row.col.f32.bf16.bf16.f32 "
                        "{%0,%1,%2,%3}, {%4,%5,%6,%7}, {%8,%9}, {%0,%1,%2,%3};"
                        : "+f"(acc[i][j][0]), "+f"(acc[i][j][1]),
                          "+f"(acc[i][j][2]), "+f"(acc[i][j][3])
                        : "r"(a[i][0]), "r"(a[i][1]), "r"(a[i][2]), "r"(a[i][3]),
                          "r"(bb0), "r"(bb1));
                }
        }

        #pragma unroll
        for (int i = 0; i < 4; ++i) {
            const int m0 = m_base + i * 16 + quad;
            const size_t r0 = (size_t)(t * TILE_M + m0) * PRE_N;
            const size_t r1 = (size_t)(t * TILE_M + m0 + 8) * PRE_N;
            #pragma unroll
            for (int j = 0; j < 4; ++j) {
                const int n = n_base + j * 8 + qlane * 2;
                __nv_bfloat162 p = __floats2bfloat162_rn(acc[i][j][0] + bb[j].x,
                                                         acc[i][j][1] + bb[j].y);
                __nv_bfloat162 q = __floats2bfloat162_rn(acc[i][j][2] + bb[j].x,
                                                         acc[i][j][3] + bb[j].y);
                *reinterpret_cast<__nv_bfloat162*>(&g_uv[r0 + n]) = p;
                *reinterpret_cast<__nv_bfloat162*>(&g_uv[r1 + n]) = q;
            }
        }
        __syncthreads();
    }
}

// ---------------- Stage B: per-edge loss + fused finalization ----------------
__global__ __launch_bounds__(EDGE_THREADS, 2)
void hx_edge(const float* __restrict__ alpha,
             const float* __restrict__ W2,
             const float* __restrict__ b2,
             const int* __restrict__ row,
             const int* __restrict__ col,
             const int* __restrict__ label,
             int E, float* __restrict__ out)
{
    __shared__ double s_dsum;
    const int tid  = threadIdx.x;
    const int lane = tid & 31;
    const int warp = tid >> 5;
    if (tid == 0) s_dsum = 0.0;
    __syncthreads();

    const int sub = lane >> 3;         // edge within group (0..3)
    const int sl  = lane & 7;          // lane within edge (0..7)
    const int ch0 = sl * 16;           // 16 channels per lane

    __nv_bfloat162 al2[8];
    float wa[16], wb[16];
    #pragma unroll
    for (int i = 0; i < 8; ++i)
        al2[i] = __floats2bfloat162_rn(__ldg(&alpha[ch0 + 2 * i]),
                                       __ldg(&alpha[ch0 + 2 * i + 1]));
    #pragma unroll
    for (int i = 0; i < 16; ++i) {
        wa[i] = __ldg(&W2[(ch0 + i) * 2]);
        wb[i] = __ldg(&W2[(ch0 + i) * 2 + 1]);
    }
    const float bias0 = b2[0], bias1 = b2[1];
    const __nv_bfloat162 z2 = __floats2bfloat162_rn(0.f, 0.f);

    const int gw = blockIdx.x * (EDGE_THREADS / 32) + warp;
    const int nw = gridDim.x * (EDGE_THREADS / 32);
    const int NG = (E + 3) >> 2;       // groups of 4 edges

    double dsum = 0.0;

    if (gw < NG) {
        int e0 = gw * 4 + sub; if (e0 >= E) e0 = E - 1;
        int la = 0, lb = 0;
        uint4 Ua, Ub, Va, Vb;
        {
            const int rc = __ldg(&row[e0]), cc = __ldg(&col[e0]);
            la = __ldg(&label[rc]); lb = __ldg(&label[cc]);
            const __nv_bfloat16* uP = &g_uv[(size_t)rc * PRE_N + ch0];
            const __nv_bfloat16* vP = &g_uv[(size_t)cc * PRE_N + 128 + ch0];
            Ua = *reinterpret_cast<const uint4*>(uP);
            Ub = *reinterpret_cast<const uint4*>(uP + 8);
            Va = *reinterpret_cast<const uint4*>(vP);
            Vb = *reinterpret_cast<const uint4*>(vP + 8);
        }
        int rn = 0, cn = 0;
        if (gw + nw < NG) {
            int e1 = (gw + nw) * 4 + sub; if (e1 >= E) e1 = E - 1;
            rn = __ldg(&row[e1]); cn = __ldg(&col[e1]);
        }

        for (int g = gw; g < NG; g += nw) {
            const int g1 = g + nw;

            uint4 nUa, nUb, nVa, nVb;
            int lan = 0, lbn = 0;
            if (g1 < NG) {
                const __nv_bfloat16* uP = &g_uv[(size_t)rn * PRE_N + ch0];
                const __nv_bfloat16* vP = &g_uv[(size_t)cn * PRE_N + 128 + ch0];
                nUa = *reinterpret_cast<const uint4*>(uP);
                nUb = *reinterpret_cast<const uint4*>(uP + 8);
                nVa = *reinterpret_cast<const uint4*>(vP);
                nVb = *reinterpret_cast<const uint4*>(vP + 8);
                lan = __ldg(&label[rn]);
                lbn = __ldg(&label[cn]);
            } else {
                nUa = make_uint4(0,0,0,0); nUb = nUa; nVa = nUa; nVb = nUa;
            }
            int rn2 = 0, cn2 = 0;
            if (g + 2 * nw < NG) {
                int e2 = (g + 2 * nw) * 4 + sub; if (e2 >= E) e2 = E - 1;
                rn2 = __ldg(&row[e2]); cn2 = __ldg(&col[e2]);
            }

            float p0 = 0.f, p1 = 0.f;
            const uint32_t uw[8] = {Ua.x, Ua.y, Ua.z, Ua.w, Ub.x, Ub.y, Ub.z, Ub.w};
            const uint32_t vw[8] = {Va.x, Va.y, Va.z, Va.w, Vb.x, Vb.y, Vb.z, Vb.w};
            #pragma unroll
            for (int i = 0; i < 8; ++i) {
                const __nv_bfloat162 u2 = *reinterpret_cast<const __nv_bfloat162*>(&uw[i]);
                const __nv_bfloat162 v2 = *reinterpret_cast<const __nv_bfloat162*>(&vw[i]);
                const __nv_bfloat162 h2 = __hadd2(u2, v2);
                const __nv_bfloat162 ph2 =
                    __hfma2(al2[i], __hmin2(h2, z2), __hmax2(h2, z2));
                const float2 f = __bfloat1622float2(ph2);
                p0 = fmaf(f.x, wa[2 * i], p0);      p1 = fmaf(f.x, wb[2 * i], p1);
                p0 = fmaf(f.y, wa[2 * i + 1], p0);  p1 = fmaf(f.y, wb[2 * i + 1], p1);
            }
            #pragma unroll
            for (int off = 4; off > 0; off >>= 1) {
                p0 += __shfl_xor_sync(0xffffffffu, p0, off);
                p1 += __shfl_xor_sync(0xffffffffu, p1, off);
            }
            if (sl == 0) {
                const int ecur = g * 4 + sub;
                if (ecur < E) {
                    const float l0 = p0 + bias0;
                    const float l1 = p1 + bias1;
                    const float mx  = fmaxf(l0, l1);
                    const float lse = mx + log1pf(expf(-fabsf(l0 - l1)));
                    dsum += (double)(((la == lb) ? l1 : l0) - lse);
                }
            }

            Ua = nUa; Ub = nUb; Va = nVa; Vb = nVb;
            la = lan; lb = lbn;
            rn = rn2; cn = cn2;
        }
    }

    if (sl == 0) atomicAdd(&s_dsum, dsum);
    __syncthreads();
    if (tid == 0) {
        atomicAdd(&g_loss_sum, s_dsum);
        __threadfence();
        const unsigned int n = atomicAdd(&g_cnt, 1u);
        if (n == gridDim.x - 1) {
            const double total = atomicAdd(&g_loss_sum, 0.0);   // ordered read
            out[0] = (float)(-total / (double)E);
        }
    }
}

extern "C" void kernel_launch(void* const* d_in, const int* in_sizes, int n_in,
                              void* d_out, int out_size) {
    const float* feature = (const float*)d_in[0];
    const float* W1      = (const float*)d_in[1];
    const float* b1      = (const float*)d_in[2];
    const float* alpha   = (const float*)d_in[3];
    const float* W2      = (const float*)d_in[4];
    const float* b2      = (const float*)d_in[5];
    const int*   row     = (const int*)d_in[6];
    const int*   col     = (const int*)d_in[7];
    const int*   label   = (const int*)d_in[8];
    const int E  = in_sizes[6];
    const int nf = in_sizes[0];
    float* out = (float*)d_out;

    int sms = 148;
    cudaDeviceGetAttribute(&sms, cudaDevAttrMultiProcessorCount, 0);
    cudaFuncSetAttribute(hx_pre_gemm,
                         cudaFuncAttributeMaxDynamicSharedMemorySize, PRE_DSMEM);

    const int n4 = nf / 4;
    hx_prep<<<(n4 + W1_ELEMS + 255) / 256, 256>>>(feature, W1, n4);

    const int nnodes = nf / NHID;
    const int ntiles = (nnodes + TILE_M - 1) / TILE_M;
    hx_pre_gemm<<<sms, PRE_THREADS, PRE_DSMEM>>>(b1, ntiles);

    hx_edge<<<sms * 2, EDGE_THREADS>>>(alpha, W2, b2, row, col, label, E, out);
}